// round 13
// baseline (speedup 1.0000x reference)
#include <cuda_runtime.h>

#define T_STEPS 64
#define N_INJ 8
#define SID 7
#define BLOCK 256
#define GRID 256          // 256 CTAs x 128 rows = 32768

#define SM_T    0
#define SM_W1D  256
#define SM_B1F  512                     // [8 nt][32 lane] uint4 = 4096
#define SM_B2H  4608                    // [4 kt][32] uint4 = 2048
#define SM_B2L  6656                    // 2048
#define SM_SE   8704                    // 128 rows x 16 f = 8192
#define SM_CG   16896                   // 8 warps x 4096
#define SM_TOTAL (SM_CG + 8*4096)       // 49664 B ; x2 CTAs = 99328 < 228K

typedef unsigned u32;

__device__ __forceinline__ void bf16split2(float x0, float x1, u32& h, u32& l) {
    asm("cvt.rn.bf16x2.f32 %0, %1, %2;" : "=r"(h) : "f"(x1), "f"(x0));
    float h0 = __uint_as_float(h << 16);
    float h1 = __uint_as_float(h & 0xffff0000u);
    asm("cvt.rn.bf16x2.f32 %0, %1, %2;" : "=r"(l) : "f"(x1 - h1), "f"(x0 - h0));
}
__device__ __forceinline__ float tanhap(float x) {
    float r; asm("tanh.approx.f32 %0,%1;" : "=f"(r) : "f"(x)); return r;
}
__device__ __forceinline__ void mma4(float& c0, float& c1, float& c2, float& c3,
                                     const u32* a, u32 b0, u32 b1) {
    asm volatile("mma.sync.aligned.m16n8k16.row.col.f32.bf16.bf16.f32 "
        "{%0,%1,%2,%3},{%4,%5,%6,%7},{%8,%9},{%0,%1,%2,%3};"
        : "+f"(c0), "+f"(c1), "+f"(c2), "+f"(c3)
        : "r"(a[0]), "r"(a[1]), "r"(a[2]), "r"(a[3]), "r"(b0), "r"(b1));
}

// one MLP eval for 16 rows: ys[8] (C-frag) -> ko[8]
__device__ __forceinline__ void feval(
    float tv, const float* __restrict__ ys, float* __restrict__ ko,
    const float* __restrict__ b2q, const char* __restrict__ smem,
    const char* __restrict__ cgT,
    const float* __restrict__ itm, const float* __restrict__ idn,
    int g, int c, int lane)
{
    float dose = 0.f;
    #pragma unroll
    for (int n = 0; n < N_INJ; n++) {
        float d = tv - itm[n];
        dose += idn[n] * __expf(-0.5f * d * d);
    }
    dose = fminf(fmaxf(dose, 0.f), 100.f);
    float d0 = __shfl_sync(0xffffffffu, dose, g);
    float d1 = __shfl_sync(0xffffffffu, dose, g + 8);

    u32 a1h[4], a1l[4];
    bf16split2(ys[0], ys[1], a1h[0], a1l[0]);
    bf16split2(ys[2], ys[3], a1h[1], a1l[1]);
    bf16split2(ys[4], ys[5], a1h[2], a1l[2]);
    bf16split2(ys[6], ys[7], a1h[3], a1l[3]);

    u32 a2h[16], a2l[16];
    #pragma unroll
    for (int nt = 0; nt < 8; nt++) {
        float4 cg = *(const float4*)(cgT + nt * 512);
        float2 wd = *(const float2*)(smem + SM_W1D + nt * 32 + c * 8);
        float z0 = fmaf(d0, wd.x, cg.x);
        float z1 = fmaf(d0, wd.y, cg.y);
        float z2 = fmaf(d1, wd.x, cg.z);
        float z3 = fmaf(d1, wd.y, cg.w);
        uint4 bf = *(const uint4*)(smem + SM_B1F + nt * 512 + lane * 16);
        mma4(z0, z1, z2, z3, a1h, bf.x, bf.y);
        mma4(z0, z1, z2, z3, a1h, bf.z, bf.w);
        mma4(z0, z1, z2, z3, a1l, bf.x, bf.y);
        float t0 = tanhap(z0), t1 = tanhap(z1);
        float t2 = tanhap(z2), t3 = tanhap(z3);
        int base = (nt >> 1) * 4 + (nt & 1) * 2;
        bf16split2(t0, t1, a2h[base], a2l[base]);
        bf16split2(t2, t3, a2h[base + 1], a2l[base + 1]);
    }
    float cA0 = b2q[0], cA1 = b2q[1], cA2 = cA0, cA3 = cA1;
    float cB0 = b2q[2], cB1 = b2q[3], cB2 = cB0, cB3 = cB1;
    #pragma unroll
    for (int kt = 0; kt < 4; kt++) {
        uint4 bh = *(const uint4*)(smem + SM_B2H + kt * 512 + lane * 16);
        uint4 bl = *(const uint4*)(smem + SM_B2L + kt * 512 + lane * 16);
        mma4(cA0, cA1, cA2, cA3, a2h + kt * 4, bh.x, bh.y);
        mma4(cA0, cA1, cA2, cA3, a2h + kt * 4, bl.x, bl.y);
        mma4(cA0, cA1, cA2, cA3, a2l + kt * 4, bh.x, bh.y);
        mma4(cB0, cB1, cB2, cB3, a2h + kt * 4, bh.z, bh.w);
        mma4(cB0, cB1, cB2, cB3, a2h + kt * 4, bl.z, bl.w);
        mma4(cB0, cB1, cB2, cB3, a2l + kt * 4, bh.z, bh.w);
    }
    ko[0] = cA0; ko[1] = cA1; ko[2] = cA2; ko[3] = cA3;
    ko[4] = cB0; ko[5] = cB1; ko[6] = cB2; ko[7] = cB3;
}

__device__ __forceinline__ void writeout(
    const float* __restrict__ h, const float* __restrict__ wrq, float brv,
    int rbase, int g, int c, int step, float* __restrict__ out)
{
    #pragma unroll
    for (int rh = 0; rh < 2; rh++) {
        float p = h[rh * 2 + 0] * wrq[0] + h[rh * 2 + 1] * wrq[1]
                + h[4 + rh * 2 + 0] * wrq[2] + h[4 + rh * 2 + 1] * wrq[3];
        p += __shfl_xor_sync(0xffffffffu, p, 1);
        p += __shfl_xor_sync(0xffffffffu, p, 2);
        if (c == 0)
            out[(rbase + g + 8 * rh) * T_STEPS + step] = fmaxf(brv + p, 0.f);
    }
}

extern "C" __global__ void __launch_bounds__(BLOCK, 2)
neural_ode_66236985639756(
    const float* __restrict__ t_g,  const float* __restrict__ sf_g,
    const float* __restrict__ it_g, const float* __restrict__ id_g,
    const float* __restrict__ W_se, const float* __restrict__ b_se,
    const float* __restrict__ W_i,  const float* __restrict__ b_i,
    const float* __restrict__ W1,   const float* __restrict__ b1,
    const float* __restrict__ W2,   const float* __restrict__ b2,
    const float* __restrict__ Wr,   const float* __restrict__ br,
    float* __restrict__ out)
{
    extern __shared__ __align__(16) char smem[];
    float* smT = (float*)(smem + SM_T);
    float* seA = (float*)(smem + SM_SE);
    const int tid = threadIdx.x;
    const int wid = tid >> 5;
    const int lane = tid & 31;
    const int g = lane >> 2;
    const int c = lane & 3;
    const int rbase = blockIdx.x * 128 + wid * 16;   // warp owns 16 rows
    const int ro = rbase + (lane & 15);              // own row (dupl. 16-31)

    for (int i = tid; i < T_STEPS; i += BLOCK) smT[i] = t_g[i];

    // weight fragments -> smem (one copy per CTA, built by warp 0)
    if (wid == 0) {
        #pragma unroll
        for (int nt = 0; nt < 8; nt++) {
            uint4 v;
            bf16split2(W1[(2 * c) * 64 + 8 * nt + g],
                       W1[(2 * c + 1) * 64 + 8 * nt + g], v.x, v.z);
            bf16split2(W1[(2 * c + 8) * 64 + 8 * nt + g],
                       W1[(2 * c + 9) * 64 + 8 * nt + g], v.y, v.w);
            *(uint4*)(smem + SM_B1F + nt * 512 + lane * 16) = v;
        }
        #pragma unroll
        for (int kt = 0; kt < 4; kt++) {
            uint4 vh, vl;
            int o0 = g, o1 = 8 + g;
            bf16split2(W2[(16 * kt + 2 * c) * 16 + o0],
                       W2[(16 * kt + 2 * c + 1) * 16 + o0], vh.x, vl.x);
            bf16split2(W2[(16 * kt + 2 * c + 8) * 16 + o0],
                       W2[(16 * kt + 2 * c + 9) * 16 + o0], vh.y, vl.y);
            bf16split2(W2[(16 * kt + 2 * c) * 16 + o1],
                       W2[(16 * kt + 2 * c + 1) * 16 + o1], vh.z, vl.z);
            bf16split2(W2[(16 * kt + 2 * c + 8) * 16 + o1],
                       W2[(16 * kt + 2 * c + 9) * 16 + o1], vh.w, vl.w);
            *(uint4*)(smem + SM_B2H + kt * 512 + lane * 16) = vh;
            *(uint4*)(smem + SM_B2L + kt * 512 + lane * 16) = vl;
        }
    }
    if (tid < 4) {
        #pragma unroll
        for (int nt = 0; nt < 8; nt++)
            *(float2*)(smem + SM_W1D + nt * 32 + tid * 8) =
                make_float2(W1[32 * 64 + 8 * nt + 2 * tid],
                            W1[32 * 64 + 8 * nt + 2 * tid + 1]);
    }

    // own-row static embed -> smem (lanes 16-31 duplicate same rows: benign)
    {
        float sfv[SID];
        #pragma unroll
        for (int i = 0; i < SID; i++) sfv[i] = sf_g[ro * SID + i];
        #pragma unroll
        for (int o = 0; o < 16; o++) {
            float acc = b_se[o];
            #pragma unroll
            for (int i = 0; i < SID; i++) acc += sfv[i] * W_se[i * 16 + o];
            seA[(wid * 16 + (lane & 15)) * 16 + o] = fmaxf(acc, 0.f);
        }
    }
    __syncthreads();

    // h0 in C-frag layout (16 rows)
    float h[8];
    #pragma unroll
    for (int e = 0; e < 8; e++) {
        int col = 2 * c + (e & 1) + ((e >> 2) & 1) * 8;
        int rl = wid * 16 + g + ((e >> 1) & 1) * 8;
        float acc = b_i[col];
        #pragma unroll
        for (int i = 0; i < 16; i++) acc += seA[rl * 16 + i] * W_i[i * 16 + col];
        h[e] = acc;
    }
    // cg (b1 + se@W1[16:32]) into C-frag-ordered smem
    const char* cgT = smem + SM_CG + wid * 4096 + lane * 16;
    for (int nt = 0; nt < 8; nt++) {
        float v[4];
        #pragma unroll
        for (int q = 0; q < 4; q++) {
            int j = 8 * nt + 2 * c + (q & 1);
            int rl = wid * 16 + g + (q >> 1) * 8;
            float acc = b1[j];
            #pragma unroll
            for (int i = 0; i < 16; i++) acc += seA[rl * 16 + i] * W1[(16 + i) * 64 + j];
            v[q] = acc;
        }
        *(float4*)(smem + SM_CG + wid * 4096 + nt * 512 + lane * 16)
            = make_float4(v[0], v[1], v[2], v[3]);
    }

    float b2q[4] = { b2[2 * c], b2[2 * c + 1], b2[2 * c + 8], b2[2 * c + 9] };
    float wrq[4] = { Wr[2 * c], Wr[2 * c + 1], Wr[2 * c + 8], Wr[2 * c + 9] };
    const float brv = br[0];

    float itm[N_INJ], idn[N_INJ];
    #pragma unroll
    for (int n = 0; n < N_INJ; n++) {
        itm[n] = it_g[ro * N_INJ + n];
        idn[n] = id_g[ro * N_INJ + n];
    }
    __syncthreads();

    writeout(h, wrq, brv, rbase, g, c, 0, out);

    const float A21 = 0.2f, A31 = 0.075f, A32 = 0.225f;
    const float A41 = (float)(44.0/45.0), A42 = (float)(-56.0/15.0), A43 = (float)(32.0/9.0);
    const float A51 = (float)(19372.0/6561.0), A52 = (float)(-25360.0/2187.0),
                A53 = (float)(64448.0/6561.0), A54 = (float)(-212.0/729.0);
    const float A61 = (float)(9017.0/3168.0), A62 = (float)(-355.0/33.0),
                A63 = (float)(46732.0/5247.0), A64 = (float)(49.0/176.0),
                A65 = (float)(-5103.0/18656.0);
    const float B1c = (float)(35.0/384.0), B3c = (float)(500.0/1113.0),
                B4c = (float)(125.0/192.0), B5c = (float)(-2187.0/6784.0),
                B6c = (float)(11.0/84.0);
    const float C2 = 0.2f, C3 = 0.3f, C4 = 0.8f, C5 = (float)(8.0/9.0);

    float k1[8], k2[8], k3[8], k4[8], k5[8], y[8];

    #pragma unroll 1
    for (int step = 0; step < T_STEPS - 1; ++step) {
        float t0 = smT[step], t1 = smT[step + 1];
        float dt = (t1 - t0) * 0.5f;
        #pragma unroll 1
        for (int sub = 0; sub < 2; ++sub) {
            float tv = t0 + sub * dt;
            feval(tv, h, k1, b2q, smem, cgT, itm, idn, g, c, lane);
            #pragma unroll
            for (int i = 0; i < 8; i++) y[i] = fmaf(dt * A21, k1[i], h[i]);
            feval(tv + C2 * dt, y, k2, b2q, smem, cgT, itm, idn, g, c, lane);
            #pragma unroll
            for (int i = 0; i < 8; i++)
                y[i] = fmaf(dt * A31, k1[i], fmaf(dt * A32, k2[i], h[i]));
            feval(tv + C3 * dt, y, k3, b2q, smem, cgT, itm, idn, g, c, lane);
            #pragma unroll
            for (int i = 0; i < 8; i++) {
                float a = fmaf(dt * A43, k3[i], h[i]);
                a = fmaf(dt * A42, k2[i], a);
                y[i] = fmaf(dt * A41, k1[i], a);
            }
            feval(tv + C4 * dt, y, k4, b2q, smem, cgT, itm, idn, g, c, lane);
            #pragma unroll
            for (int i = 0; i < 8; i++) {
                float a = fmaf(dt * A54, k4[i], h[i]);
                a = fmaf(dt * A53, k3[i], a);
                a = fmaf(dt * A52, k2[i], a);
                y[i] = fmaf(dt * A51, k1[i], a);
            }
            feval(tv + C5 * dt, y, k5, b2q, smem, cgT, itm, idn, g, c, lane);
            #pragma unroll
            for (int i = 0; i < 8; i++) {
                float a = fmaf(dt * A65, k5[i], h[i]);
                a = fmaf(dt * A64, k4[i], a);
                a = fmaf(dt * A63, k3[i], a);
                a = fmaf(dt * A62, k2[i], a);
                y[i] = fmaf(dt * A61, k1[i], a);
            }
            feval(tv + dt, y, k2, b2q, smem, cgT, itm, idn, g, c, lane);
            #pragma unroll
            for (int i = 0; i < 8; i++) {
                float a = fmaf(dt * B6c, k2[i], h[i]);
                a = fmaf(dt * B5c, k5[i], a);
                a = fmaf(dt * B4c, k4[i], a);
                a = fmaf(dt * B3c, k3[i], a);
                h[i] = fmaf(dt * B1c, k1[i], a);
            }
        }
        writeout(h, wrq, brv, rbase, g, c, step + 1, out);
    }
}

extern "C" void kernel_launch(void* const* d_in, const int* in_sizes, int n_in,
                              void* d_out, int out_size)
{
    (void)in_sizes; (void)n_in; (void)out_size;
    cudaFuncSetAttribute(neural_ode_66236985639756,
                         cudaFuncAttributeMaxDynamicSharedMemorySize, SM_TOTAL);
    neural_ode_66236985639756<<<GRID, BLOCK, SM_TOTAL>>>(
        (const float*)d_in[0],  (const float*)d_in[1],
        (const float*)d_in[2],  (const float*)d_in[3],
        (const float*)d_in[4],  (const float*)d_in[5],
        (const float*)d_in[6],  (const float*)d_in[7],
        (const float*)d_in[8],  (const float*)d_in[9],
        (const float*)d_in[10], (const float*)d_in[11],
        (const float*)d_in[12], (const float*)d_in[13],
        (float*)d_out);
}

// round 15
// speedup vs baseline: 1.0388x; 1.0388x over previous
#include <cuda_runtime.h>

#define T_STEPS 64
#define N_INJ 8
#define SID 7
#define BLOCK 256
#define GRID 128
#define B_TOTAL 32768
#define NTIX 756              // 63 steps * 2 substeps * 6 stages

#define SM_T    0
#define SM_W1D  256
#define SM_B2H  512
#define SM_B2L  2560
#define SM_SE   4608
#define SM_CG   20992
#define SM_TOTAL (SM_CG + 8*8192)   // 86528 B

typedef unsigned u32;

__device__ float g_dose[(size_t)NTIX * B_TOTAL];   // 99 MB dose table

__device__ __forceinline__ void bf16split2(float x0, float x1, u32& h, u32& l) {
    asm("cvt.rn.bf16x2.f32 %0, %1, %2;" : "=r"(h) : "f"(x1), "f"(x0));
    float h0 = __uint_as_float(h << 16);
    float h1 = __uint_as_float(h & 0xffff0000u);
    asm("cvt.rn.bf16x2.f32 %0, %1, %2;" : "=r"(l) : "f"(x1 - h1), "f"(x0 - h0));
}
__device__ __forceinline__ float tanhap(float x) {
    float r; asm("tanh.approx.f32 %0,%1;" : "=f"(r) : "f"(x)); return r;
}
__device__ __forceinline__ void mma4(float& c0, float& c1, float& c2, float& c3,
                                     const u32* a, u32 b0, u32 b1) {
    asm volatile("mma.sync.aligned.m16n8k16.row.col.f32.bf16.bf16.f32 "
        "{%0,%1,%2,%3},{%4,%5,%6,%7},{%8,%9},{%0,%1,%2,%3};"
        : "+f"(c0), "+f"(c1), "+f"(c2), "+f"(c3)
        : "r"(a[0]), "r"(a[1]), "r"(a[2]), "r"(a[3]), "r"(b0), "r"(b1));
}

// ---- dose precompute: one thread per (row, stage-time) --------------------
__global__ void dose_kernel(const float* __restrict__ t_g,
                            const float* __restrict__ it_g,
                            const float* __restrict__ id_g)
{
    const float C[6] = { 0.f, 0.2f, 0.3f, 0.8f, (float)(8.0/9.0), 1.f };
    int row = blockIdx.x * 256 + threadIdx.x;
    int tix = blockIdx.y;
    int step = tix / 12, rem = tix % 12, sub = rem / 6, s = rem % 6;
    float t0 = t_g[step];
    float dt = (t_g[step + 1] - t0) * 0.5f;
    float tv = t0 + sub * dt + C[s] * dt;
    float dose = 0.f;
    #pragma unroll
    for (int n = 0; n < N_INJ; n++) {
        float d = tv - it_g[row * N_INJ + n];
        dose += id_g[row * N_INJ + n] * __expf(-0.5f * d * d);
    }
    g_dose[(size_t)tix * B_TOTAL + row] = fminf(fmaxf(dose, 0.f), 100.f);
}

// one MLP eval: ys[16] (C-frag state) -> ko[16]; dose preloaded per lane
__device__ __forceinline__ void feval(
    float dose, const float* __restrict__ ys, float* __restrict__ ko,
    const u32* __restrict__ b1h, const u32* __restrict__ b1l,
    const float* __restrict__ b2q, const char* __restrict__ smem,
    const char* __restrict__ cgT, int g, int c, int lane)
{
    #pragma unroll
    for (int mt = 0; mt < 2; mt++) {
        float d0 = __shfl_sync(0xffffffffu, dose, 16 * mt + g);
        float d1 = __shfl_sync(0xffffffffu, dose, 16 * mt + g + 8);
        const float* y = ys + mt * 8;
        u32 a1h[4], a1l[4];
        bf16split2(y[0], y[1], a1h[0], a1l[0]);
        bf16split2(y[2], y[3], a1h[1], a1l[1]);
        bf16split2(y[4], y[5], a1h[2], a1l[2]);
        bf16split2(y[6], y[7], a1h[3], a1l[3]);

        u32 a2h[16], a2l[16];
        #pragma unroll
        for (int nt = 0; nt < 8; nt++) {
            float4 cg = *(const float4*)(cgT + (mt * 8 + nt) * 512);
            float2 wd = *(const float2*)(smem + SM_W1D + nt * 32 + c * 8);
            float z0 = fmaf(d0, wd.x, cg.x);
            float z1 = fmaf(d0, wd.y, cg.y);
            float z2 = fmaf(d1, wd.x, cg.z);
            float z3 = fmaf(d1, wd.y, cg.w);
            mma4(z0, z1, z2, z3, a1h, b1h[nt * 2], b1h[nt * 2 + 1]);
            mma4(z0, z1, z2, z3, a1h, b1l[nt * 2], b1l[nt * 2 + 1]);
            mma4(z0, z1, z2, z3, a1l, b1h[nt * 2], b1h[nt * 2 + 1]);
            float t0 = tanhap(z0), t1 = tanhap(z1);
            float t2 = tanhap(z2), t3 = tanhap(z3);
            int base = (nt >> 1) * 4 + (nt & 1) * 2;
            bf16split2(t0, t1, a2h[base], a2l[base]);
            bf16split2(t2, t3, a2h[base + 1], a2l[base + 1]);
        }
        float cA0 = b2q[0], cA1 = b2q[1], cA2 = cA0, cA3 = cA1;
        float cB0 = b2q[2], cB1 = b2q[3], cB2 = cB0, cB3 = cB1;
        #pragma unroll
        for (int kt = 0; kt < 4; kt++) {
            uint4 bh = *(const uint4*)(smem + SM_B2H + kt * 512 + lane * 16);
            uint4 bl = *(const uint4*)(smem + SM_B2L + kt * 512 + lane * 16);
            mma4(cA0, cA1, cA2, cA3, a2h + kt * 4, bh.x, bh.y);
            mma4(cA0, cA1, cA2, cA3, a2h + kt * 4, bl.x, bl.y);
            mma4(cA0, cA1, cA2, cA3, a2l + kt * 4, bh.x, bh.y);
            mma4(cB0, cB1, cB2, cB3, a2h + kt * 4, bh.z, bh.w);
            mma4(cB0, cB1, cB2, cB3, a2h + kt * 4, bl.z, bl.w);
            mma4(cB0, cB1, cB2, cB3, a2l + kt * 4, bh.z, bh.w);
        }
        ko[mt * 8 + 0] = cA0;  ko[mt * 8 + 1] = cA1;
        ko[mt * 8 + 2] = cA2;  ko[mt * 8 + 3] = cA3;
        ko[mt * 8 + 4] = cB0;  ko[mt * 8 + 5] = cB1;
        ko[mt * 8 + 6] = cB2;  ko[mt * 8 + 7] = cB3;
    }
}

__device__ __forceinline__ void writeout(
    const float* __restrict__ h, const float* __restrict__ wrq, float brv,
    int rbase, int g, int c, int step, float* __restrict__ out)
{
    #pragma unroll
    for (int mt = 0; mt < 2; mt++)
    #pragma unroll
    for (int rh = 0; rh < 2; rh++) {
        float p = h[mt * 8 + rh * 2 + 0] * wrq[0] + h[mt * 8 + rh * 2 + 1] * wrq[1]
                + h[mt * 8 + 4 + rh * 2 + 0] * wrq[2] + h[mt * 8 + 4 + rh * 2 + 1] * wrq[3];
        p += __shfl_xor_sync(0xffffffffu, p, 1);
        p += __shfl_xor_sync(0xffffffffu, p, 2);
        if (c == 0)
            out[(rbase + 16 * mt + g + 8 * rh) * T_STEPS + step] = fmaxf(brv + p, 0.f);
    }
}

extern "C" __global__ void __launch_bounds__(BLOCK, 1)
neural_ode_66236985639756(
    const float* __restrict__ t_g,  const float* __restrict__ sf_g,
    const float* __restrict__ W_se, const float* __restrict__ b_se,
    const float* __restrict__ W_i,  const float* __restrict__ b_i,
    const float* __restrict__ W1,   const float* __restrict__ b1,
    const float* __restrict__ W2,   const float* __restrict__ b2,
    const float* __restrict__ Wr,   const float* __restrict__ br,
    float* __restrict__ out)
{
    extern __shared__ __align__(16) char smem[];
    float* smT = (float*)(smem + SM_T);
    float* seA = (float*)(smem + SM_SE);
    const int tid = threadIdx.x;
    const int wid = tid >> 5;
    const int lane = tid & 31;
    const int g = lane >> 2;
    const int c = lane & 3;
    const int rbase = blockIdx.x * BLOCK + wid * 32;
    const int ro = rbase + lane;

    for (int i = tid; i < T_STEPS; i += BLOCK) smT[i] = t_g[i];

    // layer-2 weight fragments + dose weights -> smem (one copy per CTA)
    if (wid == 0) {
        #pragma unroll
        for (int kt = 0; kt < 4; kt++) {
            uint4 vh, vl;
            int o0 = g, o1 = 8 + g;
            bf16split2(W2[(16 * kt + 2 * c) * 16 + o0],
                       W2[(16 * kt + 2 * c + 1) * 16 + o0], vh.x, vl.x);
            bf16split2(W2[(16 * kt + 2 * c + 8) * 16 + o0],
                       W2[(16 * kt + 2 * c + 9) * 16 + o0], vh.y, vl.y);
            bf16split2(W2[(16 * kt + 2 * c) * 16 + o1],
                       W2[(16 * kt + 2 * c + 1) * 16 + o1], vh.z, vl.z);
            bf16split2(W2[(16 * kt + 2 * c + 8) * 16 + o1],
                       W2[(16 * kt + 2 * c + 9) * 16 + o1], vh.w, vl.w);
            *(uint4*)(smem + SM_B2H + kt * 512 + lane * 16) = vh;
            *(uint4*)(smem + SM_B2L + kt * 512 + lane * 16) = vl;
        }
    }
    if (tid < 4) {
        #pragma unroll
        for (int nt = 0; nt < 8; nt++)
            *(float2*)(smem + SM_W1D + nt * 32 + tid * 8) =
                make_float2(W1[32 * 64 + 8 * nt + 2 * tid],
                            W1[32 * 64 + 8 * nt + 2 * tid + 1]);
    }

    // own-row static embed -> smem
    {
        float sfv[SID];
        #pragma unroll
        for (int i = 0; i < SID; i++) sfv[i] = sf_g[ro * SID + i];
        #pragma unroll
        for (int o = 0; o < 16; o++) {
            float acc = b_se[o];
            #pragma unroll
            for (int i = 0; i < SID; i++) acc += sfv[i] * W_se[i * 16 + o];
            seA[(wid * 32 + lane) * 16 + o] = fmaxf(acc, 0.f);
        }
    }
    __syncthreads();

    // h0 in C-frag state layout
    float h[16];
    #pragma unroll
    for (int mt = 0; mt < 2; mt++)
    #pragma unroll
    for (int e = 0; e < 8; e++) {
        int col = 2 * c + (e & 1) + ((e >> 2) & 1) * 8;
        int rl = wid * 32 + 16 * mt + g + ((e >> 1) & 1) * 8;
        float acc = b_i[col];
        #pragma unroll
        for (int i = 0; i < 16; i++) acc += seA[rl * 16 + i] * W_i[i * 16 + col];
        h[mt * 8 + e] = acc;
    }
    // cg (b1 + se@W1[16:32]) into C-frag-ordered smem
    const char* cgT = smem + SM_CG + wid * 8192 + lane * 16;
    for (int mt = 0; mt < 2; mt++)
    for (int nt = 0; nt < 8; nt++) {
        float v[4];
        #pragma unroll
        for (int q = 0; q < 4; q++) {
            int j = 8 * nt + 2 * c + (q & 1);
            int rl = wid * 32 + 16 * mt + g + (q >> 1) * 8;
            float acc = b1[j];
            #pragma unroll
            for (int i = 0; i < 16; i++) acc += seA[rl * 16 + i] * W1[(16 + i) * 64 + j];
            v[q] = acc;
        }
        *(float4*)(smem + SM_CG + (wid * 16 + mt * 8 + nt) * 512 + lane * 16)
            = make_float4(v[0], v[1], v[2], v[3]);
    }

    // register-resident layer-1 B fragments
    u32 b1h[16], b1l[16];
    #pragma unroll
    for (int nt = 0; nt < 8; nt++) {
        bf16split2(W1[(2 * c) * 64 + 8 * nt + g], W1[(2 * c + 1) * 64 + 8 * nt + g],
                   b1h[nt * 2], b1l[nt * 2]);
        bf16split2(W1[(2 * c + 8) * 64 + 8 * nt + g], W1[(2 * c + 9) * 64 + 8 * nt + g],
                   b1h[nt * 2 + 1], b1l[nt * 2 + 1]);
    }
    float b2q[4] = { b2[2 * c], b2[2 * c + 1], b2[2 * c + 8], b2[2 * c + 9] };
    float wrq[4] = { Wr[2 * c], Wr[2 * c + 1], Wr[2 * c + 8], Wr[2 * c + 9] };
    const float brv = br[0];
    __syncthreads();

    writeout(h, wrq, brv, rbase, g, c, 0, out);

    const float A21 = 0.2f, A31 = 0.075f, A32 = 0.225f;
    const float A41 = (float)(44.0/45.0), A42 = (float)(-56.0/15.0), A43 = (float)(32.0/9.0);
    const float A51 = (float)(19372.0/6561.0), A52 = (float)(-25360.0/2187.0),
                A53 = (float)(64448.0/6561.0), A54 = (float)(-212.0/729.0);
    const float A61 = (float)(9017.0/3168.0), A62 = (float)(-355.0/33.0),
                A63 = (float)(46732.0/5247.0), A64 = (float)(49.0/176.0),
                A65 = (float)(-5103.0/18656.0);
    const float B1c = (float)(35.0/384.0), B3c = (float)(500.0/1113.0),
                B4c = (float)(125.0/192.0), B5c = (float)(-2187.0/6784.0),
                B6c = (float)(11.0/84.0);

    float k1[16], k2[16], k3[16], k4[16], k5[16], y[16];

    #pragma unroll 1
    for (int step = 0; step < T_STEPS - 1; ++step) {
        float t0 = smT[step], t1 = smT[step + 1];
        float dt = (t1 - t0) * 0.5f;
        #pragma unroll 1
        for (int sub = 0; sub < 2; ++sub) {
            // prefetch all 6 stage doses for this substep (coalesced)
            int base = (step * 2 + sub) * 6;
            float d6[6];
            #pragma unroll
            for (int s = 0; s < 6; s++)
                d6[s] = g_dose[(size_t)(base + s) * B_TOTAL + ro];

            feval(d6[0], h, k1, b1h, b1l, b2q, smem, cgT, g, c, lane);
            #pragma unroll
            for (int i = 0; i < 16; i++) y[i] = fmaf(dt * A21, k1[i], h[i]);
            feval(d6[1], y, k2, b1h, b1l, b2q, smem, cgT, g, c, lane);
            #pragma unroll
            for (int i = 0; i < 16; i++)
                y[i] = fmaf(dt * A31, k1[i], fmaf(dt * A32, k2[i], h[i]));
            feval(d6[2], y, k3, b1h, b1l, b2q, smem, cgT, g, c, lane);
            #pragma unroll
            for (int i = 0; i < 16; i++) {
                float a = fmaf(dt * A43, k3[i], h[i]);
                a = fmaf(dt * A42, k2[i], a);
                y[i] = fmaf(dt * A41, k1[i], a);
            }
            feval(d6[3], y, k4, b1h, b1l, b2q, smem, cgT, g, c, lane);
            #pragma unroll
            for (int i = 0; i < 16; i++) {
                float a = fmaf(dt * A54, k4[i], h[i]);
                a = fmaf(dt * A53, k3[i], a);
                a = fmaf(dt * A52, k2[i], a);
                y[i] = fmaf(dt * A51, k1[i], a);
            }
            feval(d6[4], y, k5, b1h, b1l, b2q, smem, cgT, g, c, lane);
            #pragma unroll
            for (int i = 0; i < 16; i++) {
                float a = fmaf(dt * A65, k5[i], h[i]);
                a = fmaf(dt * A64, k4[i], a);
                a = fmaf(dt * A63, k3[i], a);
                a = fmaf(dt * A62, k2[i], a);
                y[i] = fmaf(dt * A61, k1[i], a);
            }
            feval(d6[5], y, k2, b1h, b1l, b2q, smem, cgT, g, c, lane);
            #pragma unroll
            for (int i = 0; i < 16; i++) {
                float a = fmaf(dt * B6c, k2[i], h[i]);
                a = fmaf(dt * B5c, k5[i], a);
                a = fmaf(dt * B4c, k4[i], a);
                a = fmaf(dt * B3c, k3[i], a);
                h[i] = fmaf(dt * B1c, k1[i], a);
            }
        }
        writeout(h, wrq, brv, rbase, g, c, step + 1, out);
    }
}

extern "C" void kernel_launch(void* const* d_in, const int* in_sizes, int n_in,
                              void* d_out, int out_size)
{
    (void)in_sizes; (void)n_in; (void)out_size;

    dim3 dgrid(B_TOTAL / 256, NTIX);
    dose_kernel<<<dgrid, 256>>>((const float*)d_in[0],
                                (const float*)d_in[2],
                                (const float*)d_in[3]);

    cudaFuncSetAttribute(neural_ode_66236985639756,
                         cudaFuncAttributeMaxDynamicSharedMemorySize, SM_TOTAL);
    neural_ode_66236985639756<<<GRID, BLOCK, SM_TOTAL>>>(
        (const float*)d_in[0],  (const float*)d_in[1],
        (const float*)d_in[4],  (const float*)d_in[5],
        (const float*)d_in[6],  (const float*)d_in[7],
        (const float*)d_in[8],  (const float*)d_in[9],
        (const float*)d_in[10], (const float*)d_in[11],
        (const float*)d_in[12], (const float*)d_in[13],
        (float*)d_out);
}

// round 16
// speedup vs baseline: 1.2635x; 1.2162x over previous
#include <cuda_runtime.h>

#define T_STEPS 64
#define N_INJ 8
#define SID 7
#define BLOCK 256
#define GRID 128

#define SM_T  0
#define SM_SE 1024
#define SM_CG (SM_SE + 16384)
#define SM_TOTAL (SM_CG + 65536)

typedef unsigned u32;

__device__ __forceinline__ void bf16split2(float x0, float x1, u32& h, u32& l) {
    asm("cvt.rn.bf16x2.f32 %0, %1, %2;" : "=r"(h) : "f"(x1), "f"(x0));
    float h0 = __uint_as_float(h << 16);
    float h1 = __uint_as_float(h & 0xffff0000u);
    asm("cvt.rn.bf16x2.f32 %0, %1, %2;" : "=r"(l) : "f"(x1 - h1), "f"(x0 - h0));
}
__device__ __forceinline__ float tanhap(float x) {
    float r; asm("tanh.approx.f32 %0,%1;" : "=f"(r) : "f"(x)); return r;
}
__device__ __forceinline__ void mma4(float& c0, float& c1, float& c2, float& c3,
                                     const u32* a, u32 b0, u32 b1) {
    asm volatile("mma.sync.aligned.m16n8k16.row.col.f32.bf16.bf16.f32 "
        "{%0,%1,%2,%3},{%4,%5,%6,%7},{%8,%9},{%0,%1,%2,%3};"
        : "+f"(c0), "+f"(c1), "+f"(c2), "+f"(c3)
        : "r"(a[0]), "r"(a[1]), "r"(a[2]), "r"(a[3]), "r"(b0), "r"(b1));
}

// one MLP eval: ys[16] (C-frag state) -> ko[16]
__device__ __forceinline__ void feval(
    float tv, const float* __restrict__ ys, float* __restrict__ ko,
    const u32* __restrict__ b1h, const u32* __restrict__ b1l,
    const u32* __restrict__ b2h, const u32* __restrict__ b2l,
    const float* __restrict__ w1dA, const float* __restrict__ w1dB,
    const float* __restrict__ b2q, const char* __restrict__ cgT,
    const float* __restrict__ itm, const float* __restrict__ idn, int g)
{
    float dose = 0.f;
    #pragma unroll
    for (int n = 0; n < N_INJ; n++) {
        float d = tv - itm[n];
        dose += idn[n] * __expf(-0.5f * d * d);
    }
    dose = fminf(fmaxf(dose, 0.f), 100.f);

    #pragma unroll
    for (int mt = 0; mt < 2; mt++) {
        float d0 = __shfl_sync(0xffffffffu, dose, 16 * mt + g);
        float d1 = __shfl_sync(0xffffffffu, dose, 16 * mt + g + 8);
        const float* y = ys + mt * 8;
        u32 a1h[4], a1l[4];
        bf16split2(y[0], y[1], a1h[0], a1l[0]);
        bf16split2(y[2], y[3], a1h[1], a1l[1]);
        bf16split2(y[4], y[5], a1h[2], a1l[2]);
        bf16split2(y[6], y[7], a1h[3], a1l[3]);

        u32 a2h[16], a2l[16];
        #pragma unroll
        for (int nt = 0; nt < 8; nt++) {
            float4 cg = *(const float4*)(cgT + (mt * 8 + nt) * 512);
            float z0 = fmaf(d0, w1dA[nt], cg.x);
            float z1 = fmaf(d0, w1dB[nt], cg.y);
            float z2 = fmaf(d1, w1dA[nt], cg.z);
            float z3 = fmaf(d1, w1dB[nt], cg.w);
            mma4(z0, z1, z2, z3, a1h, b1h[nt * 2], b1h[nt * 2 + 1]);
            mma4(z0, z1, z2, z3, a1h, b1l[nt * 2], b1l[nt * 2 + 1]);
            mma4(z0, z1, z2, z3, a1l, b1h[nt * 2], b1h[nt * 2 + 1]);
            float t0 = tanhap(z0), t1 = tanhap(z1);
            float t2 = tanhap(z2), t3 = tanhap(z3);
            int base = (nt >> 1) * 4 + (nt & 1) * 2;
            bf16split2(t0, t1, a2h[base], a2l[base]);
            bf16split2(t2, t3, a2h[base + 1], a2l[base + 1]);
        }
        // layer 2: kt-halved accumulators -> 4 independent chains of depth 6
        float cA0 = b2q[0], cA1 = b2q[1], cA2 = cA0, cA3 = cA1;
        float cB0 = b2q[2], cB1 = b2q[3], cB2 = cB0, cB3 = cB1;
        float dA0 = 0.f, dA1 = 0.f, dA2 = 0.f, dA3 = 0.f;
        float dB0 = 0.f, dB1 = 0.f, dB2 = 0.f, dB3 = 0.f;
        #pragma unroll
        for (int kt = 0; kt < 2; kt++) {
            const u32* bh = b2h + kt * 4;
            const u32* bl = b2l + kt * 4;
            mma4(cA0, cA1, cA2, cA3, a2h + kt * 4, bh[0], bh[1]);
            mma4(cA0, cA1, cA2, cA3, a2h + kt * 4, bl[0], bl[1]);
            mma4(cA0, cA1, cA2, cA3, a2l + kt * 4, bh[0], bh[1]);
            mma4(cB0, cB1, cB2, cB3, a2h + kt * 4, bh[2], bh[3]);
            mma4(cB0, cB1, cB2, cB3, a2h + kt * 4, bl[2], bl[3]);
            mma4(cB0, cB1, cB2, cB3, a2l + kt * 4, bh[2], bh[3]);
        }
        #pragma unroll
        for (int kt = 2; kt < 4; kt++) {
            const u32* bh = b2h + kt * 4;
            const u32* bl = b2l + kt * 4;
            mma4(dA0, dA1, dA2, dA3, a2h + kt * 4, bh[0], bh[1]);
            mma4(dA0, dA1, dA2, dA3, a2h + kt * 4, bl[0], bl[1]);
            mma4(dA0, dA1, dA2, dA3, a2l + kt * 4, bh[0], bh[1]);
            mma4(dB0, dB1, dB2, dB3, a2h + kt * 4, bh[2], bh[3]);
            mma4(dB0, dB1, dB2, dB3, a2h + kt * 4, bl[2], bl[3]);
            mma4(dB0, dB1, dB2, dB3, a2l + kt * 4, bh[2], bh[3]);
        }
        ko[mt * 8 + 0] = cA0 + dA0;  ko[mt * 8 + 1] = cA1 + dA1;
        ko[mt * 8 + 2] = cA2 + dA2;  ko[mt * 8 + 3] = cA3 + dA3;
        ko[mt * 8 + 4] = cB0 + dB0;  ko[mt * 8 + 5] = cB1 + dB1;
        ko[mt * 8 + 6] = cB2 + dB2;  ko[mt * 8 + 7] = cB3 + dB3;
    }
}

__device__ __forceinline__ void writeout(
    const float* __restrict__ h, const float* __restrict__ wrq, float brv,
    int rbase, int g, int c, int step, float* __restrict__ out)
{
    #pragma unroll
    for (int mt = 0; mt < 2; mt++)
    #pragma unroll
    for (int rh = 0; rh < 2; rh++) {
        float p = h[mt * 8 + rh * 2 + 0] * wrq[0] + h[mt * 8 + rh * 2 + 1] * wrq[1]
                + h[mt * 8 + 4 + rh * 2 + 0] * wrq[2] + h[mt * 8 + 4 + rh * 2 + 1] * wrq[3];
        p += __shfl_xor_sync(0xffffffffu, p, 1);
        p += __shfl_xor_sync(0xffffffffu, p, 2);
        if (c == 0)
            out[(rbase + 16 * mt + g + 8 * rh) * T_STEPS + step] = fmaxf(brv + p, 0.f);
    }
}

extern "C" __global__ void __launch_bounds__(BLOCK, 1)
neural_ode_66236985639756(
    const float* __restrict__ t_g,  const float* __restrict__ sf_g,
    const float* __restrict__ it_g, const float* __restrict__ id_g,
    const float* __restrict__ W_se, const float* __restrict__ b_se,
    const float* __restrict__ W_i,  const float* __restrict__ b_i,
    const float* __restrict__ W1,   const float* __restrict__ b1,
    const float* __restrict__ W2,   const float* __restrict__ b2,
    const float* __restrict__ Wr,   const float* __restrict__ br,
    float* __restrict__ out)
{
    extern __shared__ __align__(16) char smem[];
    float* smT = (float*)(smem + SM_T);
    float* seA = (float*)(smem + SM_SE);
    const int tid = threadIdx.x;
    const int wid = tid >> 5;
    const int lane = tid & 31;
    const int g = lane >> 2;
    const int c = lane & 3;
    const int rbase = blockIdx.x * BLOCK + wid * 32;
    const int ro = rbase + lane;

    for (int i = tid; i < T_STEPS; i += BLOCK) smT[i] = t_g[i];

    // own-row static embed -> smem
    {
        float sfv[SID];
        #pragma unroll
        for (int i = 0; i < SID; i++) sfv[i] = sf_g[ro * SID + i];
        #pragma unroll
        for (int o = 0; o < 16; o++) {
            float acc = b_se[o];
            #pragma unroll
            for (int i = 0; i < SID; i++) acc += sfv[i] * W_se[i * 16 + o];
            seA[(wid * 32 + lane) * 16 + o] = fmaxf(acc, 0.f);
        }
    }
    __syncthreads();

    // h0 in C-frag state layout
    float h[16];
    #pragma unroll
    for (int mt = 0; mt < 2; mt++)
    #pragma unroll
    for (int e = 0; e < 8; e++) {
        int col = 2 * c + (e & 1) + ((e >> 2) & 1) * 8;
        int rl = wid * 32 + 16 * mt + g + ((e >> 1) & 1) * 8;
        float acc = b_i[col];
        #pragma unroll
        for (int i = 0; i < 16; i++) acc += seA[rl * 16 + i] * W_i[i * 16 + col];
        h[mt * 8 + e] = acc;
    }
    // cg (b1 + se@W1[16:32]) into C-frag-ordered smem
    const char* cgT = smem + SM_CG + wid * 8192 + lane * 16;
    for (int mt = 0; mt < 2; mt++)
    for (int nt = 0; nt < 8; nt++) {
        float v[4];
        #pragma unroll
        for (int q = 0; q < 4; q++) {
            int j = 8 * nt + 2 * c + (q & 1);
            int rl = wid * 32 + 16 * mt + g + (q >> 1) * 8;
            float acc = b1[j];
            #pragma unroll
            for (int i = 0; i < 16; i++) acc += seA[rl * 16 + i] * W1[(16 + i) * 64 + j];
            v[q] = acc;
        }
        *(float4*)(smem + SM_CG + (wid * 16 + mt * 8 + nt) * 512 + lane * 16)
            = make_float4(v[0], v[1], v[2], v[3]);
    }

    // register-resident B fragments
    u32 b1h[16], b1l[16];
    float w1dA[8], w1dB[8];
    #pragma unroll
    for (int nt = 0; nt < 8; nt++) {
        bf16split2(W1[(2 * c) * 64 + 8 * nt + g], W1[(2 * c + 1) * 64 + 8 * nt + g],
                   b1h[nt * 2], b1l[nt * 2]);
        bf16split2(W1[(2 * c + 8) * 64 + 8 * nt + g], W1[(2 * c + 9) * 64 + 8 * nt + g],
                   b1h[nt * 2 + 1], b1l[nt * 2 + 1]);
        w1dA[nt] = W1[32 * 64 + 8 * nt + 2 * c];
        w1dB[nt] = W1[32 * 64 + 8 * nt + 2 * c + 1];
    }
    u32 b2h[16], b2l[16];
    #pragma unroll
    for (int kt = 0; kt < 4; kt++)
    #pragma unroll
    for (int nt2 = 0; nt2 < 2; nt2++) {
        int o = 8 * nt2 + g;
        bf16split2(W2[(16 * kt + 2 * c) * 16 + o], W2[(16 * kt + 2 * c + 1) * 16 + o],
                   b2h[kt * 4 + nt2 * 2], b2l[kt * 4 + nt2 * 2]);
        bf16split2(W2[(16 * kt + 2 * c + 8) * 16 + o], W2[(16 * kt + 2 * c + 9) * 16 + o],
                   b2h[kt * 4 + nt2 * 2 + 1], b2l[kt * 4 + nt2 * 2 + 1]);
    }
    float b2q[4] = { b2[2 * c], b2[2 * c + 1], b2[2 * c + 8], b2[2 * c + 9] };
    float wrq[4] = { Wr[2 * c], Wr[2 * c + 1], Wr[2 * c + 8], Wr[2 * c + 9] };
    const float brv = br[0];

    float itm[N_INJ], idn[N_INJ];
    #pragma unroll
    for (int n = 0; n < N_INJ; n++) {
        itm[n] = it_g[ro * N_INJ + n];
        idn[n] = id_g[ro * N_INJ + n];
    }
    __syncthreads();

    writeout(h, wrq, brv, rbase, g, c, 0, out);

    const float A21 = 0.2f, A31 = 0.075f, A32 = 0.225f;
    const float A41 = (float)(44.0/45.0), A42 = (float)(-56.0/15.0), A43 = (float)(32.0/9.0);
    const float A51 = (float)(19372.0/6561.0), A52 = (float)(-25360.0/2187.0),
                A53 = (float)(64448.0/6561.0), A54 = (float)(-212.0/729.0);
    const float A61 = (float)(9017.0/3168.0), A62 = (float)(-355.0/33.0),
                A63 = (float)(46732.0/5247.0), A64 = (float)(49.0/176.0),
                A65 = (float)(-5103.0/18656.0);
    const float B1c = (float)(35.0/384.0), B3c = (float)(500.0/1113.0),
                B4c = (float)(125.0/192.0), B5c = (float)(-2187.0/6784.0),
                B6c = (float)(11.0/84.0);
    const float C2 = 0.2f, C3 = 0.3f, C4 = 0.8f, C5 = (float)(8.0/9.0);

    float k1[16], k2[16], k3[16], k4[16], k5[16], y[16];

    #pragma unroll 1
    for (int step = 0; step < T_STEPS - 1; ++step) {
        float t0 = smT[step], t1 = smT[step + 1];
        float dt = (t1 - t0) * 0.5f;
        #pragma unroll 1
        for (int sub = 0; sub < 2; ++sub) {
            float tv = t0 + sub * dt;
            feval(tv, h, k1, b1h, b1l, b2h, b2l, w1dA, w1dB, b2q, cgT, itm, idn, g);
            #pragma unroll
            for (int i = 0; i < 16; i++) y[i] = fmaf(dt * A21, k1[i], h[i]);
            feval(tv + C2 * dt, y, k2, b1h, b1l, b2h, b2l, w1dA, w1dB, b2q, cgT, itm, idn, g);
            #pragma unroll
            for (int i = 0; i < 16; i++)
                y[i] = fmaf(dt * A31, k1[i], fmaf(dt * A32, k2[i], h[i]));
            feval(tv + C3 * dt, y, k3, b1h, b1l, b2h, b2l, w1dA, w1dB, b2q, cgT, itm, idn, g);
            #pragma unroll
            for (int i = 0; i < 16; i++) {
                float a = fmaf(dt * A43, k3[i], h[i]);
                a = fmaf(dt * A42, k2[i], a);
                y[i] = fmaf(dt * A41, k1[i], a);
            }
            feval(tv + C4 * dt, y, k4, b1h, b1l, b2h, b2l, w1dA, w1dB, b2q, cgT, itm, idn, g);
            #pragma unroll
            for (int i = 0; i < 16; i++) {
                float a = fmaf(dt * A54, k4[i], h[i]);
                a = fmaf(dt * A53, k3[i], a);
                a = fmaf(dt * A52, k2[i], a);
                y[i] = fmaf(dt * A51, k1[i], a);
            }
            feval(tv + C5 * dt, y, k5, b1h, b1l, b2h, b2l, w1dA, w1dB, b2q, cgT, itm, idn, g);
            #pragma unroll
            for (int i = 0; i < 16; i++) {
                float a = fmaf(dt * A65, k5[i], h[i]);
                a = fmaf(dt * A64, k4[i], a);
                a = fmaf(dt * A63, k3[i], a);
                a = fmaf(dt * A62, k2[i], a);
                y[i] = fmaf(dt * A61, k1[i], a);
            }
            feval(tv + dt, y, k2, b1h, b1l, b2h, b2l, w1dA, w1dB, b2q, cgT, itm, idn, g);
            #pragma unroll
            for (int i = 0; i < 16; i++) {
                float a = fmaf(dt * B6c, k2[i], h[i]);
                a = fmaf(dt * B5c, k5[i], a);
                a = fmaf(dt * B4c, k4[i], a);
                a = fmaf(dt * B3c, k3[i], a);
                h[i] = fmaf(dt * B1c, k1[i], a);
            }
        }
        writeout(h, wrq, brv, rbase, g, c, step + 1, out);
    }
}

extern "C" void kernel_launch(void* const* d_in, const int* in_sizes, int n_in,
                              void* d_out, int out_size)
{
    (void)in_sizes; (void)n_in; (void)out_size;
    cudaFuncSetAttribute(neural_ode_66236985639756,
                         cudaFuncAttributeMaxDynamicSharedMemorySize, SM_TOTAL);
    neural_ode_66236985639756<<<GRID, BLOCK, SM_TOTAL>>>(
        (const float*)d_in[0],  (const float*)d_in[1],
        (const float*)d_in[2],  (const float*)d_in[3],
        (const float*)d_in[4],  (const float*)d_in[5],
        (const float*)d_in[6],  (const float*)d_in[7],
        (const float*)d_in[8],  (const float*)d_in[9],
        (const float*)d_in[10], (const float*)d_in[11],
        (const float*)d_in[12], (const float*)d_in[13],
        (float*)d_out);
}